// round 3
// baseline (speedup 1.0000x reference)
#include <cuda_runtime.h>
#include <cuda_bf16.h>

#define N_NODES 50000
#define N_EDGES 600000
#define N_GRAPHS 64
#define HID 128

// ---------------- scratch (static device globals; no allocation) ----------------
__device__ int   g_indeg[N_NODES];
__device__ float g_dis[N_NODES];
__device__ int   g_offs[N_NODES + 1];
__device__ int   g_fill[N_NODES];
__device__ int   g_srcs[N_EDGES];
__device__ float g_h0[(size_t)N_NODES * HID];   // GEMM output / agg input
__device__ float g_h1[(size_t)N_NODES * HID];   // agg output / next GEMM input
__device__ int   g_gstart[N_GRAPHS + 1];
__device__ float g_pooled[N_GRAPHS * HID];
__device__ float g_z[N_GRAPHS * 64];

// ---------------- graph preprocessing ----------------
__global__ void k_init() {
    for (int i = blockIdx.x * blockDim.x + threadIdx.x; i < N_NODES;
         i += gridDim.x * blockDim.x) {
        g_indeg[i] = 0;
        g_fill[i] = 0;
    }
}

__global__ void k_degree(const int* __restrict__ ei) {
    int i = blockIdx.x * blockDim.x + threadIdx.x;
    if (i >= N_EDGES) return;
    int d = ei[N_EDGES + i];
    if (d >= 0 && d < N_NODES) atomicAdd(&g_indeg[d], 1);
}

__global__ void k_dis() {
    int i = blockIdx.x * blockDim.x + threadIdx.x;
    if (i < N_NODES) g_dis[i] = rsqrtf((float)(g_indeg[i] + 1));  // +1 self-loop
}

// single-block exclusive scan of g_indeg -> g_offs (n=50000, 49 chunks of 1024)
__global__ void k_scan(int n) {
    __shared__ int wsum[32];
    __shared__ int carry_sh;
    int tid = threadIdx.x, lane = tid & 31, wid = tid >> 5;
    int carry = 0;
    for (int base = 0; base < n; base += 1024) {
        int i = base + tid;
        int v = (i < n) ? g_indeg[i] : 0;
        int s = v;
        #pragma unroll
        for (int o = 1; o < 32; o <<= 1) {
            int t = __shfl_up_sync(0xffffffffu, s, o);
            if (lane >= o) s += t;
        }
        if (lane == 31) wsum[wid] = s;
        __syncthreads();
        if (wid == 0) {
            int ws = wsum[lane];
            #pragma unroll
            for (int o = 1; o < 32; o <<= 1) {
                int t = __shfl_up_sync(0xffffffffu, ws, o);
                if (lane >= o) ws += t;
            }
            wsum[lane] = ws;
        }
        __syncthreads();
        int excl = carry + (wid > 0 ? wsum[wid - 1] : 0) + (s - v);
        if (i < n) g_offs[i] = excl;
        if (tid == 1023) carry_sh = excl + v;
        __syncthreads();
        carry = carry_sh;
        __syncthreads();
    }
    if (tid == 0) g_offs[n] = carry;
}

__global__ void k_fill(const int* __restrict__ ei) {
    int i = blockIdx.x * blockDim.x + threadIdx.x;
    if (i >= N_EDGES) return;
    int s = ei[i];
    int d = ei[N_EDGES + i];
    if (s < 0 || s >= N_NODES || d < 0 || d >= N_NODES) return;
    int pos = g_offs[d] + atomicAdd(&g_fill[d], 1);
    g_srcs[pos] = s;
}

__global__ void k_graph_bounds(const int* __restrict__ batch) {
    int i = blockIdx.x * blockDim.x + threadIdx.x;
    if (i >= N_NODES) return;
    int b = batch[i];
    if (b < 0) b = 0;
    if (b >= N_GRAPHS) b = N_GRAPHS - 1;
    int prev;
    if (i == 0) prev = -1;
    else {
        prev = batch[i - 1];
        if (prev < 0) prev = 0;
        if (prev >= N_GRAPHS) prev = N_GRAPHS - 1;
    }
    for (int g = prev + 1; g <= b; g++) g_gstart[g] = i;
    if (i == N_NODES - 1)
        for (int g = b + 1; g <= N_GRAPHS; g++) g_gstart[g] = N_NODES;
}

// ---------------- GEMMs ----------------
// layer 1: [N,6] @ [6,128] -> g_h0
__global__ void k_gemm6(const float* __restrict__ x, const float* __restrict__ W) {
    int row = blockIdx.x * 2 + (threadIdx.x >> 7);
    int c = threadIdx.x & 127;
    if (row >= N_NODES) return;
    float acc = 0.f;
    #pragma unroll
    for (int k = 0; k < 6; k++) acc += __ldg(&x[row * 6 + k]) * __ldg(&W[k * HID + c]);
    g_h0[(size_t)row * HID + c] = acc;
}

// layers 2/3: g_h1[N,128] @ W[128,128] -> g_h0 ; 32 rows x 128 cols per block
__global__ void k_gemm128(const float* __restrict__ W) {
    __shared__ float Ash[32][HID];
    int ty = threadIdx.x >> 5;   // 0..3 row group
    int tx = threadIdx.x & 31;   // 0..31 col group (4 cols each)
    int row0 = blockIdx.x * 32;
    for (int idx = threadIdx.x; idx < 32 * 32; idx += 128) {
        int r = idx >> 5, q = idx & 31;
        int row = row0 + r;
        float4 v = make_float4(0.f, 0.f, 0.f, 0.f);
        if (row < N_NODES) v = ((const float4*)(g_h1 + (size_t)row * HID))[q];
        *(float4*)&Ash[r][q * 4] = v;
    }
    __syncthreads();
    float acc[8][4];
    #pragma unroll
    for (int r = 0; r < 8; r++)
        #pragma unroll
        for (int q = 0; q < 4; q++) acc[r][q] = 0.f;
    #pragma unroll 4
    for (int k = 0; k < HID; k++) {
        float4 w = ((const float4*)(W + k * HID))[tx];
        #pragma unroll
        for (int r = 0; r < 8; r++) {
            float a = Ash[ty * 8 + r][k];
            acc[r][0] += a * w.x;
            acc[r][1] += a * w.y;
            acc[r][2] += a * w.z;
            acc[r][3] += a * w.w;
        }
    }
    #pragma unroll
    for (int r = 0; r < 8; r++) {
        int row = row0 + ty * 8 + r;
        if (row < N_NODES) {
            float4 o = make_float4(acc[r][0], acc[r][1], acc[r][2], acc[r][3]);
            ((float4*)(g_h0 + (size_t)row * HID))[tx] = o;
        }
    }
}

// ---------------- aggregation: reads g_h0, writes g_h1
// out[d] = relu( dis[d]^2*h[d] + sum_e dis[s]*dis[d]*h[s] + b )
__global__ void k_aggregate(const float* __restrict__ b) {
    int node = blockIdx.x * (blockDim.x >> 5) + (threadIdx.x >> 5);
    if (node >= N_NODES) return;
    int lane = threadIdx.x & 31;
    float dd = g_dis[node];
    float4 v = ((const float4*)(g_h0 + (size_t)node * HID))[lane];
    float s0 = dd * dd;
    float ax = v.x * s0, ay = v.y * s0, az = v.z * s0, aw = v.w * s0;
    int beg = g_offs[node], end = g_offs[node + 1];
    for (int e = beg; e < end; e++) {
        int s = g_srcs[e];
        float w = g_dis[s] * dd;
        float4 hv = ((const float4*)(g_h0 + (size_t)s * HID))[lane];
        ax += hv.x * w;
        ay += hv.y * w;
        az += hv.z * w;
        aw += hv.w * w;
    }
    float4 bb = ((const float4*)b)[lane];
    ax = fmaxf(ax + bb.x, 0.f);
    ay = fmaxf(ay + bb.y, 0.f);
    az = fmaxf(az + bb.z, 0.f);
    aw = fmaxf(aw + bb.w, 0.f);
    ((float4*)(g_h1 + (size_t)node * HID))[lane] = make_float4(ax, ay, az, aw);
}

// ---------------- pooling + MLP ----------------
__global__ void k_pool() {
    int g = blockIdx.x, c = threadIdx.x;
    int s = g_gstart[g], e = g_gstart[g + 1];
    float acc = 0.f;
    for (int i = s; i < e; i++) acc += g_h1[(size_t)i * HID + c];
    float cnt = (float)((e - s) > 1 ? (e - s) : 1);
    g_pooled[g * HID + c] = acc / cnt;
}

__global__ void k_fc1(const float* __restrict__ w, const float* __restrict__ b) {
    int g = blockIdx.x, j = threadIdx.x;  // 64 x 64
    float acc = b[j];
    #pragma unroll 8
    for (int k = 0; k < HID; k++) acc += g_pooled[g * HID + k] * w[k * 64 + j];
    g_z[g * 64 + j] = fmaxf(acc, 0.f);
}

__global__ void k_fc2(const float* __restrict__ w, const float* __restrict__ b,
                      float* __restrict__ out) {
    int g = threadIdx.x;  // 64
    float acc = b[0];
    #pragma unroll 8
    for (int j = 0; j < 64; j++) acc += g_z[g * 64 + j] * w[j];
    out[g] = acc;
}

// ---------------- launch ----------------
extern "C" void kernel_launch(void* const* d_in, const int* in_sizes, int n_in,
                              void* d_out, int out_size) {
    const float* x     = (const float*)d_in[0];
    const int*   ei    = (const int*)d_in[1];   // int64 narrowed to int32 by harness
    const int*   batch = (const int*)d_in[2];
    const float* W1 = (const float*)d_in[3];
    const float* b1 = (const float*)d_in[4];
    const float* W2 = (const float*)d_in[5];
    const float* b2 = (const float*)d_in[6];
    const float* W3 = (const float*)d_in[7];
    const float* b3 = (const float*)d_in[8];
    const float* fc1_w = (const float*)d_in[9];
    const float* fc1_b = (const float*)d_in[10];
    const float* fc2_w = (const float*)d_in[11];
    const float* fc2_b = (const float*)d_in[12];
    float* out = (float*)d_out;

    // graph structure (per-call: deterministic & self-contained)
    k_init<<<256, 256>>>();
    k_degree<<<(N_EDGES + 255) / 256, 256>>>(ei);
    k_dis<<<(N_NODES + 255) / 256, 256>>>();
    k_scan<<<1, 1024>>>(N_NODES);
    k_fill<<<(N_EDGES + 255) / 256, 256>>>(ei);
    k_graph_bounds<<<(N_NODES + 255) / 256, 256>>>(batch);

    const int AGG_BLOCKS = (N_NODES + 7) / 8;   // 8 warps/block, 1 warp/node
    const int G128_BLOCKS = (N_NODES + 31) / 32;

    // layer 1
    k_gemm6<<<(N_NODES + 1) / 2, 256>>>(x, W1);
    k_aggregate<<<AGG_BLOCKS, 256>>>(b1);
    // layer 2
    k_gemm128<<<G128_BLOCKS, 128>>>(W2);
    k_aggregate<<<AGG_BLOCKS, 256>>>(b2);
    // layer 3
    k_gemm128<<<G128_BLOCKS, 128>>>(W3);
    k_aggregate<<<AGG_BLOCKS, 256>>>(b3);

    // pool + MLP
    k_pool<<<N_GRAPHS, HID>>>();
    k_fc1<<<N_GRAPHS, 64>>>(fc1_w, fc1_b);
    k_fc2<<<1, N_GRAPHS>>>(fc2_w, fc2_b, out);
}

// round 4
// speedup vs baseline: 1.0862x; 1.0862x over previous
#include <cuda_runtime.h>
#include <cuda_bf16.h>

#define N_NODES 50000
#define N_EDGES 600000
#define N_GRAPHS 64
#define HID 128
#define SCAN_NB ((N_NODES + 255) / 256)   // 196

// ---------------- scratch (static device globals; no allocation) ----------------
__device__ int   g_indeg[N_NODES];
__device__ float g_dis[N_NODES];
__device__ int   g_offs[N_NODES + 1];
__device__ int   g_fill[N_NODES];
__device__ int   g_srcs[N_EDGES];
__device__ int   g_bsum[256];
__device__ float g_h0[(size_t)N_NODES * HID];   // GEMM output / agg input
__device__ float g_h1[(size_t)N_NODES * HID];   // agg output / next GEMM input
__device__ int   g_gstart[N_GRAPHS + 1];
__device__ float g_pooled[N_GRAPHS * HID];
__device__ float g_z[N_GRAPHS * 64];

// ---------------- graph preprocessing ----------------
__global__ void k_init() {
    for (int i = blockIdx.x * blockDim.x + threadIdx.x; i < N_NODES;
         i += gridDim.x * blockDim.x) {
        g_indeg[i] = 0;
        g_fill[i] = 0;
    }
}

__global__ void k_degree(const int* __restrict__ ei) {
    int i = blockIdx.x * blockDim.x + threadIdx.x;
    if (i >= N_EDGES) return;
    int d = ei[N_EDGES + i];
    if (d >= 0 && d < N_NODES) atomicAdd(&g_indeg[d], 1);
}

__global__ void k_dis() {
    int i = blockIdx.x * blockDim.x + threadIdx.x;
    if (i < N_NODES) g_dis[i] = rsqrtf((float)(g_indeg[i] + 1));  // +1 self-loop
}

// ---- hierarchical scan: level 1 (per 256-chunk exclusive scan + block sums)
__global__ void k_scan1() {
    __shared__ int wsum[8];
    int tid = threadIdx.x, lane = tid & 31, wid = tid >> 5;
    int i = blockIdx.x * 256 + tid;
    int v = (i < N_NODES) ? g_indeg[i] : 0;
    int s = v;
    #pragma unroll
    for (int o = 1; o < 32; o <<= 1) {
        int t = __shfl_up_sync(0xffffffffu, s, o);
        if (lane >= o) s += t;
    }
    if (lane == 31) wsum[wid] = s;
    __syncthreads();
    if (tid == 0) {
        int run = 0;
        #pragma unroll
        for (int j = 0; j < 8; j++) { int t = wsum[j]; wsum[j] = run; run += t; }
        g_bsum[blockIdx.x] = run;   // block total
    }
    __syncthreads();
    int excl = wsum[wid] + (s - v);
    if (i < N_NODES) g_offs[i] = excl;
}

// ---- level 2: exclusive scan of SCAN_NB block sums (single 256-thread block)
__global__ void k_scan2() {
    __shared__ int wsum[8];
    int tid = threadIdx.x, lane = tid & 31, wid = tid >> 5;
    int v = (tid < SCAN_NB) ? g_bsum[tid] : 0;
    int s = v;
    #pragma unroll
    for (int o = 1; o < 32; o <<= 1) {
        int t = __shfl_up_sync(0xffffffffu, s, o);
        if (lane >= o) s += t;
    }
    if (lane == 31) wsum[wid] = s;
    __syncthreads();
    if (tid == 0) {
        int run = 0;
        #pragma unroll
        for (int j = 0; j < 8; j++) { int t = wsum[j]; wsum[j] = run; run += t; }
    }
    __syncthreads();
    int excl = wsum[wid] + (s - v);
    if (tid < SCAN_NB) g_bsum[tid] = excl;
    if (tid == SCAN_NB - 1) g_offs[N_NODES] = excl + v;   // grand total
}

// ---- level 3: add block offsets
__global__ void k_scan3() {
    int i = blockIdx.x * 256 + threadIdx.x;
    if (i < N_NODES) g_offs[i] += g_bsum[blockIdx.x];
}

__global__ void k_fill(const int* __restrict__ ei) {
    int i = blockIdx.x * blockDim.x + threadIdx.x;
    if (i >= N_EDGES) return;
    int s = ei[i];
    int d = ei[N_EDGES + i];
    if (s < 0 || s >= N_NODES || d < 0 || d >= N_NODES) return;
    int pos = g_offs[d] + atomicAdd(&g_fill[d], 1);
    g_srcs[pos] = s;
}

__global__ void k_graph_bounds(const int* __restrict__ batch) {
    int i = blockIdx.x * blockDim.x + threadIdx.x;
    if (i >= N_NODES) return;
    int b = batch[i];
    if (b < 0) b = 0;
    if (b >= N_GRAPHS) b = N_GRAPHS - 1;
    int prev;
    if (i == 0) prev = -1;
    else {
        prev = batch[i - 1];
        if (prev < 0) prev = 0;
        if (prev >= N_GRAPHS) prev = N_GRAPHS - 1;
    }
    for (int g = prev + 1; g <= b; g++) g_gstart[g] = i;
    if (i == N_NODES - 1)
        for (int g = b + 1; g <= N_GRAPHS; g++) g_gstart[g] = N_NODES;
}

// ---------------- GEMMs ----------------
// layer 1: [N,6] @ [6,128] -> g_h0
__global__ void k_gemm6(const float* __restrict__ x, const float* __restrict__ W) {
    int row = blockIdx.x * 2 + (threadIdx.x >> 7);
    int c = threadIdx.x & 127;
    if (row >= N_NODES) return;
    float acc = 0.f;
    #pragma unroll
    for (int k = 0; k < 6; k++) acc += __ldg(&x[row * 6 + k]) * __ldg(&W[k * HID + c]);
    g_h0[(size_t)row * HID + c] = acc;
}

// packed fp32x2 FMA (SASS FFMA2) — ptxas only emits via explicit PTX
__device__ __forceinline__ unsigned long long ffma2(unsigned long long a,
                                                    unsigned long long b,
                                                    unsigned long long c) {
    unsigned long long d;
    asm("fma.rn.f32x2 %0, %1, %2, %3;" : "=l"(d) : "l"(a), "l"(b), "l"(c));
    return d;
}

// layers 2/3: g_h1[N,128] @ W[128,128] -> g_h0 ; 32 rows x 128 cols per block
// A-tile stored duplicated {a,a} in smem so the inner loop is LDS.64 + FFMA2 only.
__global__ void k_gemm128(const float* __restrict__ W) {
    __shared__ unsigned long long Ash[32][HID];   // 32 KB
    int ty = threadIdx.x >> 5;   // 0..3 : row group (8 rows)
    int tx = threadIdx.x & 31;   // 0..31 : col group (4 cols = 1 ulonglong2)
    int row0 = blockIdx.x * 32;

    // cooperative A-tile load: float4 per thread, store duplicated
    for (int idx = threadIdx.x; idx < 32 * 32; idx += 128) {
        int r = idx >> 5, q = idx & 31;
        int row = row0 + r;
        float4 v = make_float4(0.f, 0.f, 0.f, 0.f);
        if (row < N_NODES) v = ((const float4*)(g_h1 + (size_t)row * HID))[q];
        unsigned long long p0, p1, p2, p3;
        asm("mov.b64 %0, {%1, %1};" : "=l"(p0) : "r"(__float_as_uint(v.x)));
        asm("mov.b64 %0, {%1, %1};" : "=l"(p1) : "r"(__float_as_uint(v.y)));
        asm("mov.b64 %0, {%1, %1};" : "=l"(p2) : "r"(__float_as_uint(v.z)));
        asm("mov.b64 %0, {%1, %1};" : "=l"(p3) : "r"(__float_as_uint(v.w)));
        Ash[r][q * 4 + 0] = p0;
        Ash[r][q * 4 + 1] = p1;
        Ash[r][q * 4 + 2] = p2;
        Ash[r][q * 4 + 3] = p3;
    }
    __syncthreads();

    unsigned long long acc[8][2];
    #pragma unroll
    for (int r = 0; r < 8; r++) { acc[r][0] = 0ull; acc[r][1] = 0ull; }

    #pragma unroll 4
    for (int k = 0; k < HID; k++) {
        ulonglong2 w2 = ((const ulonglong2*)(W + (size_t)k * HID))[tx];
        #pragma unroll
        for (int r = 0; r < 8; r++) {
            unsigned long long a = Ash[ty * 8 + r][k];
            acc[r][0] = ffma2(a, w2.x, acc[r][0]);
            acc[r][1] = ffma2(a, w2.y, acc[r][1]);
        }
    }

    #pragma unroll
    for (int r = 0; r < 8; r++) {
        int row = row0 + ty * 8 + r;
        if (row < N_NODES) {
            ulonglong2 o; o.x = acc[r][0]; o.y = acc[r][1];
            ((ulonglong2*)(g_h0 + (size_t)row * HID))[tx] = o;
        }
    }
}

// ---------------- aggregation: reads g_h0, writes g_h1
// out[d] = relu( dis[d]^2*h[d] + sum_e dis[s]*dis[d]*h[s] + b )
__global__ void k_aggregate(const float* __restrict__ b) {
    int node = blockIdx.x * (blockDim.x >> 5) + (threadIdx.x >> 5);
    if (node >= N_NODES) return;
    int lane = threadIdx.x & 31;
    float dd = g_dis[node];
    float4 v = ((const float4*)(g_h0 + (size_t)node * HID))[lane];
    float s0 = dd * dd;
    float ax = v.x * s0, ay = v.y * s0, az = v.z * s0, aw = v.w * s0;
    int beg = g_offs[node], end = g_offs[node + 1];
    for (int e = beg; e < end; e++) {
        int s = g_srcs[e];
        float w = g_dis[s] * dd;
        float4 hv = ((const float4*)(g_h0 + (size_t)s * HID))[lane];
        ax += hv.x * w;
        ay += hv.y * w;
        az += hv.z * w;
        aw += hv.w * w;
    }
    float4 bb = ((const float4*)b)[lane];
    ax = fmaxf(ax + bb.x, 0.f);
    ay = fmaxf(ay + bb.y, 0.f);
    az = fmaxf(az + bb.z, 0.f);
    aw = fmaxf(aw + bb.w, 0.f);
    ((float4*)(g_h1 + (size_t)node * HID))[lane] = make_float4(ax, ay, az, aw);
}

// ---------------- pooling + MLP ----------------
__global__ void k_pool() {
    int g = blockIdx.x, c = threadIdx.x;
    int s = g_gstart[g], e = g_gstart[g + 1];
    float acc = 0.f;
    for (int i = s; i < e; i++) acc += g_h1[(size_t)i * HID + c];
    float cnt = (float)((e - s) > 1 ? (e - s) : 1);
    g_pooled[g * HID + c] = acc / cnt;
}

__global__ void k_fc1(const float* __restrict__ w, const float* __restrict__ b) {
    int g = blockIdx.x, j = threadIdx.x;  // 64 x 64
    float acc = b[j];
    #pragma unroll 8
    for (int k = 0; k < HID; k++) acc += g_pooled[g * HID + k] * w[k * 64 + j];
    g_z[g * 64 + j] = fmaxf(acc, 0.f);
}

__global__ void k_fc2(const float* __restrict__ w, const float* __restrict__ b,
                      float* __restrict__ out) {
    int g = threadIdx.x;  // 64
    float acc = b[0];
    #pragma unroll 8
    for (int j = 0; j < 64; j++) acc += g_z[g * 64 + j] * w[j];
    out[g] = acc;
}

// ---------------- launch ----------------
extern "C" void kernel_launch(void* const* d_in, const int* in_sizes, int n_in,
                              void* d_out, int out_size) {
    const float* x     = (const float*)d_in[0];
    const int*   ei    = (const int*)d_in[1];   // int64 narrowed to int32 by harness
    const int*   batch = (const int*)d_in[2];
    const float* W1 = (const float*)d_in[3];
    const float* b1 = (const float*)d_in[4];
    const float* W2 = (const float*)d_in[5];
    const float* b2 = (const float*)d_in[6];
    const float* W3 = (const float*)d_in[7];
    const float* b3 = (const float*)d_in[8];
    const float* fc1_w = (const float*)d_in[9];
    const float* fc1_b = (const float*)d_in[10];
    const float* fc2_w = (const float*)d_in[11];
    const float* fc2_b = (const float*)d_in[12];
    float* out = (float*)d_out;

    // graph structure (per-call: deterministic & self-contained)
    k_init<<<256, 256>>>();
    k_degree<<<(N_EDGES + 255) / 256, 256>>>(ei);
    k_dis<<<(N_NODES + 255) / 256, 256>>>();
    k_scan1<<<SCAN_NB, 256>>>();
    k_scan2<<<1, 256>>>();
    k_scan3<<<SCAN_NB, 256>>>();
    k_fill<<<(N_EDGES + 255) / 256, 256>>>(ei);
    k_graph_bounds<<<(N_NODES + 255) / 256, 256>>>(batch);

    const int AGG_BLOCKS = (N_NODES + 7) / 8;   // 8 warps/block, 1 warp/node
    const int G128_BLOCKS = (N_NODES + 31) / 32;

    // layer 1
    k_gemm6<<<(N_NODES + 1) / 2, 256>>>(x, W1);
    k_aggregate<<<AGG_BLOCKS, 256>>>(b1);
    // layer 2
    k_gemm128<<<G128_BLOCKS, 128>>>(W2);
    k_aggregate<<<AGG_BLOCKS, 256>>>(b2);
    // layer 3
    k_gemm128<<<G128_BLOCKS, 128>>>(W3);
    k_aggregate<<<AGG_BLOCKS, 256>>>(b3);

    // pool + MLP
    k_pool<<<N_GRAPHS, HID>>>();
    k_fc1<<<N_GRAPHS, 64>>>(fc1_w, fc1_b);
    k_fc2<<<1, N_GRAPHS>>>(fc2_w, fc2_b, out);
}

// round 5
// speedup vs baseline: 1.1954x; 1.1005x over previous
#include <cuda_runtime.h>
#include <cuda_bf16.h>

#define N_NODES 50000
#define N_EDGES 600000
#define N_GRAPHS 64
#define HID 128
#define SCAN_NB ((N_NODES + 255) / 256)   // 196

// ---------------- scratch (static device globals; no allocation) ----------------
__device__ int   g_indeg[N_NODES];
__device__ float g_dis[N_NODES];
__device__ int   g_offs[N_NODES + 1];
__device__ int   g_fill[N_NODES];
__device__ int   g_srcs[N_EDGES];
__device__ int   g_bsum[256];
__device__ float g_ax[(size_t)N_NODES * 6];     // aggregated input features
__device__ float g_h0[(size_t)N_NODES * HID];   // agg output  (GEMM input)
__device__ float g_h1[(size_t)N_NODES * HID];   // GEMM output (agg input / pool input)
__device__ int   g_gstart[N_GRAPHS + 1];
__device__ float g_pooled[N_GRAPHS * HID];
__device__ float g_z[N_GRAPHS * 64];

// ---------------- graph preprocessing ----------------
__global__ void k_init() {
    for (int i = blockIdx.x * blockDim.x + threadIdx.x; i < N_NODES;
         i += gridDim.x * blockDim.x) {
        g_indeg[i] = 0;
        g_fill[i] = 0;
    }
}

__global__ void k_degree(const int* __restrict__ ei) {
    int i = blockIdx.x * blockDim.x + threadIdx.x;
    if (i >= N_EDGES) return;
    int d = ei[N_EDGES + i];
    if (d >= 0 && d < N_NODES) atomicAdd(&g_indeg[d], 1);
}

// ---- hierarchical scan level 1 (+ fused g_dis computation)
__global__ void k_scan1() {
    __shared__ int wsum[8];
    int tid = threadIdx.x, lane = tid & 31, wid = tid >> 5;
    int i = blockIdx.x * 256 + tid;
    int v = (i < N_NODES) ? g_indeg[i] : 0;
    if (i < N_NODES) g_dis[i] = rsqrtf((float)(v + 1));  // +1 self-loop
    int s = v;
    #pragma unroll
    for (int o = 1; o < 32; o <<= 1) {
        int t = __shfl_up_sync(0xffffffffu, s, o);
        if (lane >= o) s += t;
    }
    if (lane == 31) wsum[wid] = s;
    __syncthreads();
    if (tid == 0) {
        int run = 0;
        #pragma unroll
        for (int j = 0; j < 8; j++) { int t = wsum[j]; wsum[j] = run; run += t; }
        g_bsum[blockIdx.x] = run;
    }
    __syncthreads();
    int excl = wsum[wid] + (s - v);
    if (i < N_NODES) g_offs[i] = excl;
}

// ---- level 2: exclusive scan of block sums
__global__ void k_scan2() {
    __shared__ int wsum[8];
    int tid = threadIdx.x, lane = tid & 31, wid = tid >> 5;
    int v = (tid < SCAN_NB) ? g_bsum[tid] : 0;
    int s = v;
    #pragma unroll
    for (int o = 1; o < 32; o <<= 1) {
        int t = __shfl_up_sync(0xffffffffu, s, o);
        if (lane >= o) s += t;
    }
    if (lane == 31) wsum[wid] = s;
    __syncthreads();
    if (tid == 0) {
        int run = 0;
        #pragma unroll
        for (int j = 0; j < 8; j++) { int t = wsum[j]; wsum[j] = run; run += t; }
    }
    __syncthreads();
    int excl = wsum[wid] + (s - v);
    if (tid < SCAN_NB) g_bsum[tid] = excl;
    if (tid == SCAN_NB - 1) g_offs[N_NODES] = excl + v;
}

// ---- level 3: add block offsets
__global__ void k_scan3() {
    int i = blockIdx.x * 256 + threadIdx.x;
    if (i < N_NODES) g_offs[i] += g_bsum[blockIdx.x];
}

__global__ void k_fill(const int* __restrict__ ei) {
    int i = blockIdx.x * blockDim.x + threadIdx.x;
    if (i >= N_EDGES) return;
    int s = ei[i];
    int d = ei[N_EDGES + i];
    if (s < 0 || s >= N_NODES || d < 0 || d >= N_NODES) return;
    int pos = g_offs[d] + atomicAdd(&g_fill[d], 1);
    g_srcs[pos] = s;
}

__global__ void k_graph_bounds(const int* __restrict__ batch) {
    int i = blockIdx.x * blockDim.x + threadIdx.x;
    if (i >= N_NODES) return;
    int b = batch[i];
    if (b < 0) b = 0;
    if (b >= N_GRAPHS) b = N_GRAPHS - 1;
    int prev;
    if (i == 0) prev = -1;
    else {
        prev = batch[i - 1];
        if (prev < 0) prev = 0;
        if (prev >= N_GRAPHS) prev = N_GRAPHS - 1;
    }
    for (int g = prev + 1; g <= b; g++) g_gstart[g] = i;
    if (i == N_NODES - 1)
        for (int g = b + 1; g <= N_GRAPHS; g++) g_gstart[g] = N_NODES;
}

// ---------------- layer 1 aggregation on raw 6-dim input (agg-first reorder)
// g_ax[d] = dis[d]^2 * x[d] + sum_e dis[s]*dis[d]*x[s]
__global__ void k_agg_x(const float* __restrict__ x) {
    int node = blockIdx.x * blockDim.x + threadIdx.x;
    if (node >= N_NODES) return;
    float dd = g_dis[node];
    float s0 = dd * dd;
    const float2* xr = (const float2*)(x + node * 6);
    float2 a0 = xr[0], a1 = xr[1], a2 = xr[2];
    a0.x *= s0; a0.y *= s0; a1.x *= s0; a1.y *= s0; a2.x *= s0; a2.y *= s0;
    int beg = g_offs[node], end = g_offs[node + 1];
    for (int e = beg; e < end; e++) {
        int s = g_srcs[e];
        float w = g_dis[s] * dd;
        const float2* xs = (const float2*)(x + s * 6);
        float2 v0 = xs[0], v1 = xs[1], v2 = xs[2];
        a0.x += v0.x * w; a0.y += v0.y * w;
        a1.x += v1.x * w; a1.y += v1.y * w;
        a2.x += v2.x * w; a2.y += v2.y * w;
    }
    float2* o = (float2*)(g_ax + node * 6);
    o[0] = a0; o[1] = a1; o[2] = a2;
}

// ---------------- GEMMs ----------------
// layer 1: g_ax[N,6] @ W1[6,128] + b1, relu -> g_h1
__global__ void k_gemm6(const float* __restrict__ W, const float* __restrict__ b) {
    int row = blockIdx.x * 2 + (threadIdx.x >> 7);
    int c = threadIdx.x & 127;
    if (row >= N_NODES) return;
    float acc = __ldg(&b[c]);
    #pragma unroll
    for (int k = 0; k < 6; k++) acc += g_ax[row * 6 + k] * __ldg(&W[k * HID + c]);
    g_h1[(size_t)row * HID + c] = fmaxf(acc, 0.f);
}

// packed fp32x2 FMA (SASS FFMA2)
__device__ __forceinline__ unsigned long long ffma2(unsigned long long a,
                                                    unsigned long long b,
                                                    unsigned long long c) {
    unsigned long long d;
    asm("fma.rn.f32x2 %0, %1, %2, %3;" : "=l"(d) : "l"(a), "l"(b), "l"(c));
    return d;
}

// layers 2/3: g_h0[N,128] @ W[128,128] + b, relu -> g_h1
__global__ void k_gemm128(const float* __restrict__ W, const float* __restrict__ b) {
    __shared__ unsigned long long Ash[32][HID];   // 32 KB, duplicated {a,a}
    int ty = threadIdx.x >> 5;   // 0..3 : row group (8 rows)
    int tx = threadIdx.x & 31;   // 0..31 : col group (4 cols)
    int row0 = blockIdx.x * 32;

    for (int idx = threadIdx.x; idx < 32 * 32; idx += 128) {
        int r = idx >> 5, q = idx & 31;
        int row = row0 + r;
        float4 v = make_float4(0.f, 0.f, 0.f, 0.f);
        if (row < N_NODES) v = ((const float4*)(g_h0 + (size_t)row * HID))[q];
        unsigned long long p0, p1, p2, p3;
        asm("mov.b64 %0, {%1, %1};" : "=l"(p0) : "r"(__float_as_uint(v.x)));
        asm("mov.b64 %0, {%1, %1};" : "=l"(p1) : "r"(__float_as_uint(v.y)));
        asm("mov.b64 %0, {%1, %1};" : "=l"(p2) : "r"(__float_as_uint(v.z)));
        asm("mov.b64 %0, {%1, %1};" : "=l"(p3) : "r"(__float_as_uint(v.w)));
        Ash[r][q * 4 + 0] = p0;
        Ash[r][q * 4 + 1] = p1;
        Ash[r][q * 4 + 2] = p2;
        Ash[r][q * 4 + 3] = p3;
    }
    __syncthreads();

    unsigned long long acc[8][2];
    #pragma unroll
    for (int r = 0; r < 8; r++) { acc[r][0] = 0ull; acc[r][1] = 0ull; }

    #pragma unroll 4
    for (int k = 0; k < HID; k++) {
        ulonglong2 w2 = ((const ulonglong2*)(W + (size_t)k * HID))[tx];
        #pragma unroll
        for (int r = 0; r < 8; r++) {
            unsigned long long a = Ash[ty * 8 + r][k];
            acc[r][0] = ffma2(a, w2.x, acc[r][0]);
            acc[r][1] = ffma2(a, w2.y, acc[r][1]);
        }
    }

    float4 bb = ((const float4*)b)[tx];
    #pragma unroll
    for (int r = 0; r < 8; r++) {
        int row = row0 + ty * 8 + r;
        if (row < N_NODES) {
            float2 lo = *(float2*)&acc[r][0];
            float2 hi = *(float2*)&acc[r][1];
            float4 o;
            o.x = fmaxf(lo.x + bb.x, 0.f);
            o.y = fmaxf(lo.y + bb.y, 0.f);
            o.z = fmaxf(hi.x + bb.z, 0.f);
            o.w = fmaxf(hi.y + bb.w, 0.f);
            ((float4*)(g_h1 + (size_t)row * HID))[tx] = o;
        }
    }
}

// ---------------- 128-dim aggregation (pure linear): reads g_h1, writes g_h0
// g_h0[d] = dis[d]^2*h[d] + sum_e dis[s]*dis[d]*h[s]
__global__ void k_aggregate() {
    int node = blockIdx.x * (blockDim.x >> 5) + (threadIdx.x >> 5);
    if (node >= N_NODES) return;
    int lane = threadIdx.x & 31;
    float dd = g_dis[node];
    float4 v = ((const float4*)(g_h1 + (size_t)node * HID))[lane];
    float s0 = dd * dd;
    float ax = v.x * s0, ay = v.y * s0, az = v.z * s0, aw = v.w * s0;
    int beg = g_offs[node], end = g_offs[node + 1];
    for (int e = beg; e < end; e++) {
        int s = g_srcs[e];
        float w = g_dis[s] * dd;
        float4 hv = ((const float4*)(g_h1 + (size_t)s * HID))[lane];
        ax += hv.x * w;
        ay += hv.y * w;
        az += hv.z * w;
        aw += hv.w * w;
    }
    ((float4*)(g_h0 + (size_t)node * HID))[lane] = make_float4(ax, ay, az, aw);
}

// ---------------- pooling + MLP ----------------
__global__ void k_pool() {
    int g = blockIdx.x, c = threadIdx.x;
    int s = g_gstart[g], e = g_gstart[g + 1];
    float acc = 0.f;
    for (int i = s; i < e; i++) acc += g_h1[(size_t)i * HID + c];
    float cnt = (float)((e - s) > 1 ? (e - s) : 1);
    g_pooled[g * HID + c] = acc / cnt;
}

__global__ void k_fc1(const float* __restrict__ w, const float* __restrict__ b) {
    int g = blockIdx.x, j = threadIdx.x;  // 64 x 64
    float acc = b[j];
    #pragma unroll 8
    for (int k = 0; k < HID; k++) acc += g_pooled[g * HID + k] * w[k * 64 + j];
    g_z[g * 64 + j] = fmaxf(acc, 0.f);
}

__global__ void k_fc2(const float* __restrict__ w, const float* __restrict__ b,
                      float* __restrict__ out) {
    int g = threadIdx.x;  // 64
    float acc = b[0];
    #pragma unroll 8
    for (int j = 0; j < 64; j++) acc += g_z[g * 64 + j] * w[j];
    out[g] = acc;
}

// ---------------- launch ----------------
extern "C" void kernel_launch(void* const* d_in, const int* in_sizes, int n_in,
                              void* d_out, int out_size) {
    const float* x     = (const float*)d_in[0];
    const int*   ei    = (const int*)d_in[1];   // int64 narrowed to int32 by harness
    const int*   batch = (const int*)d_in[2];
    const float* W1 = (const float*)d_in[3];
    const float* b1 = (const float*)d_in[4];
    const float* W2 = (const float*)d_in[5];
    const float* b2 = (const float*)d_in[6];
    const float* W3 = (const float*)d_in[7];
    const float* b3 = (const float*)d_in[8];
    const float* fc1_w = (const float*)d_in[9];
    const float* fc1_b = (const float*)d_in[10];
    const float* fc2_w = (const float*)d_in[11];
    const float* fc2_b = (const float*)d_in[12];
    float* out = (float*)d_out;

    // graph structure (per-call: deterministic & self-contained)
    k_init<<<256, 256>>>();
    k_degree<<<(N_EDGES + 255) / 256, 256>>>(ei);
    k_scan1<<<SCAN_NB, 256>>>();
    k_scan2<<<1, 256>>>();
    k_scan3<<<SCAN_NB, 256>>>();
    k_fill<<<(N_EDGES + 255) / 256, 256>>>(ei);
    k_graph_bounds<<<(N_NODES + 255) / 256, 256>>>(batch);

    const int AGG_BLOCKS = (N_NODES + 7) / 8;   // 8 warps/block, 1 warp/node
    const int G128_BLOCKS = (N_NODES + 31) / 32;

    // layer 1: agg(x) @ W1 + b1, relu
    k_agg_x<<<(N_NODES + 255) / 256, 256>>>(x);
    k_gemm6<<<(N_NODES + 1) / 2, 256>>>(W1, b1);
    // layer 2: agg(h) @ W2 + b2, relu
    k_aggregate<<<AGG_BLOCKS, 256>>>();
    k_gemm128<<<G128_BLOCKS, 128>>>(W2, b2);
    // layer 3: agg(h) @ W3 + b3, relu
    k_aggregate<<<AGG_BLOCKS, 256>>>();
    k_gemm128<<<G128_BLOCKS, 128>>>(W3, b3);

    // pool + MLP
    k_pool<<<N_GRAPHS, HID>>>();
    k_fc1<<<N_GRAPHS, 64>>>(fc1_w, fc1_b);
    k_fc2<<<1, N_GRAPHS>>>(fc2_w, fc2_b, out);
}

// round 7
// speedup vs baseline: 1.2446x; 1.0412x over previous
#include <cuda_runtime.h>
#include <cuda_fp16.h>
#include <cuda_bf16.h>

#define N_NODES 50000
#define N_EDGES 600000
#define N_GRAPHS 64
#define HID 128
#define SCAN_NB ((N_NODES + 255) / 256)   // 196

__device__ __forceinline__ unsigned int h2_as_u32(__half2 h) {
    return *reinterpret_cast<unsigned int*>(&h);
}
__device__ __forceinline__ __half2 u32_as_h2(unsigned int u) {
    return *reinterpret_cast<__half2*>(&u);
}

// ---------------- scratch (static device globals; no allocation) ----------------
__device__ int    g_indeg[N_NODES];
__device__ float  g_dis[N_NODES];
__device__ int    g_offs[N_NODES + 1];    // chunk-local exclusive scans
__device__ int    g_fill[N_NODES];
__device__ int    g_srcs[N_EDGES];
__device__ int    g_bsum[256];            // per-chunk global offsets
__device__ float  g_ax[(size_t)N_NODES * 6];     // aggregated input features
__device__ float  g_h0[(size_t)N_NODES * HID];   // agg output (fp32, GEMM input)
__device__ __half g_h1h[(size_t)N_NODES * HID];  // GEMM output (fp16, gathered)
__device__ int    g_gstart[N_GRAPHS + 1];
__device__ float  g_pooled[N_GRAPHS * HID];
__device__ float  g_z[N_GRAPHS * 64];

__device__ __forceinline__ int real_off(int i) { return g_offs[i] + g_bsum[i >> 8]; }

// ---------------- graph preprocessing ----------------
__global__ void k_init() {
    for (int i = blockIdx.x * blockDim.x + threadIdx.x; i < N_NODES;
         i += gridDim.x * blockDim.x) {
        g_indeg[i] = 0;
        g_fill[i] = 0;
    }
}

__global__ void k_degree(const int* __restrict__ ei) {
    int i = blockIdx.x * blockDim.x + threadIdx.x;
    if (i >= N_EDGES) return;
    int d = ei[N_EDGES + i];
    if (d >= 0 && d < N_NODES) atomicAdd(&g_indeg[d], 1);
}

// ---- scan level 1 (chunk-local exclusive scan; also writes g_dis)
__global__ void k_scan1() {
    __shared__ int wsum[8];
    int tid = threadIdx.x, lane = tid & 31, wid = tid >> 5;
    int i = blockIdx.x * 256 + tid;
    int v = (i < N_NODES) ? g_indeg[i] : 0;
    if (i < N_NODES) g_dis[i] = rsqrtf((float)(v + 1));  // +1 self-loop
    int s = v;
    #pragma unroll
    for (int o = 1; o < 32; o <<= 1) {
        int t = __shfl_up_sync(0xffffffffu, s, o);
        if (lane >= o) s += t;
    }
    if (lane == 31) wsum[wid] = s;
    __syncthreads();
    if (tid == 0) {
        int run = 0;
        #pragma unroll
        for (int j = 0; j < 8; j++) { int t = wsum[j]; wsum[j] = run; run += t; }
        g_bsum[blockIdx.x] = run;   // chunk total (scanned in level 2)
    }
    __syncthreads();
    int excl = wsum[wid] + (s - v);
    if (i <= N_NODES) g_offs[i] = excl;   // includes i == N_NODES (chunk-local)
}

// ---- level 2: exclusive scan of chunk totals
__global__ void k_scan2() {
    __shared__ int wsum[8];
    int tid = threadIdx.x, lane = tid & 31, wid = tid >> 5;
    int v = (tid < SCAN_NB) ? g_bsum[tid] : 0;
    int s = v;
    #pragma unroll
    for (int o = 1; o < 32; o <<= 1) {
        int t = __shfl_up_sync(0xffffffffu, s, o);
        if (lane >= o) s += t;
    }
    if (lane == 31) wsum[wid] = s;
    __syncthreads();
    if (tid == 0) {
        int run = 0;
        #pragma unroll
        for (int j = 0; j < 8; j++) { int t = wsum[j]; wsum[j] = run; run += t; }
    }
    __syncthreads();
    int excl = wsum[wid] + (s - v);
    if (tid < SCAN_NB) g_bsum[tid] = excl;
}

__global__ void k_fill(const int* __restrict__ ei) {
    int i = blockIdx.x * blockDim.x + threadIdx.x;
    if (i >= N_EDGES) return;
    int s = ei[i];
    int d = ei[N_EDGES + i];
    if (s < 0 || s >= N_NODES || d < 0 || d >= N_NODES) return;
    int pos = real_off(d) + atomicAdd(&g_fill[d], 1);
    g_srcs[pos] = s;
}

__global__ void k_graph_bounds(const int* __restrict__ batch) {
    int i = blockIdx.x * blockDim.x + threadIdx.x;
    if (i >= N_NODES) return;
    int b = batch[i];
    if (b < 0) b = 0;
    if (b >= N_GRAPHS) b = N_GRAPHS - 1;
    int prev;
    if (i == 0) prev = -1;
    else {
        prev = batch[i - 1];
        if (prev < 0) prev = 0;
        if (prev >= N_GRAPHS) prev = N_GRAPHS - 1;
    }
    for (int g = prev + 1; g <= b; g++) g_gstart[g] = i;
    if (i == N_NODES - 1)
        for (int g = b + 1; g <= N_GRAPHS; g++) g_gstart[g] = N_NODES;
}

// ---------------- layer 1 aggregation on raw 6-dim input
__global__ void k_agg_x(const float* __restrict__ x) {
    int node = blockIdx.x * blockDim.x + threadIdx.x;
    if (node >= N_NODES) return;
    float dd = g_dis[node];
    float s0 = dd * dd;
    const float2* xr = (const float2*)(x + node * 6);
    float2 a0 = xr[0], a1 = xr[1], a2 = xr[2];
    a0.x *= s0; a0.y *= s0; a1.x *= s0; a1.y *= s0; a2.x *= s0; a2.y *= s0;
    int beg = real_off(node), end = real_off(node + 1);
    for (int e = beg; e < end; e++) {
        int s = g_srcs[e];
        float w = g_dis[s] * dd;
        const float2* xs = (const float2*)(x + s * 6);
        float2 v0 = xs[0], v1 = xs[1], v2 = xs[2];
        a0.x += v0.x * w; a0.y += v0.y * w;
        a1.x += v1.x * w; a1.y += v1.y * w;
        a2.x += v2.x * w; a2.y += v2.y * w;
    }
    float2* o = (float2*)(g_ax + node * 6);
    o[0] = a0; o[1] = a1; o[2] = a2;
}

// ---------------- GEMMs ----------------
// layer 1: g_ax[N,6] @ W1[6,128] + b1, relu -> g_h1h (fp16)
__global__ void k_gemm6(const float* __restrict__ W, const float* __restrict__ b) {
    int row = blockIdx.x * 4 + (threadIdx.x >> 6);
    int j = threadIdx.x & 63;        // col pair index
    if (row >= N_NODES) return;
    int c0 = j * 2;
    float acc0 = __ldg(&b[c0]), acc1 = __ldg(&b[c0 + 1]);
    #pragma unroll
    for (int k = 0; k < 6; k++) {
        float a = g_ax[row * 6 + k];
        acc0 += a * __ldg(&W[k * HID + c0]);
        acc1 += a * __ldg(&W[k * HID + c0 + 1]);
    }
    __half2 h = __floats2half2_rn(fmaxf(acc0, 0.f), fmaxf(acc1, 0.f));
    ((__half2*)(g_h1h + (size_t)row * HID))[j] = h;
}

// packed fp32x2 FMA (SASS FFMA2)
__device__ __forceinline__ unsigned long long ffma2(unsigned long long a,
                                                    unsigned long long b,
                                                    unsigned long long c) {
    unsigned long long d;
    asm("fma.rn.f32x2 %0, %1, %2, %3;" : "=l"(d) : "l"(a), "l"(b), "l"(c));
    return d;
}

// layers 2/3: g_h0[N,128] @ W[128,128] + b, relu -> g_h1h (fp16)
__global__ void k_gemm128(const float* __restrict__ W, const float* __restrict__ b) {
    __shared__ unsigned long long Ash[32][HID];   // 32 KB, duplicated {a,a}
    int ty = threadIdx.x >> 5;   // 0..3 : row group (8 rows)
    int tx = threadIdx.x & 31;   // 0..31 : col group (4 cols)
    int row0 = blockIdx.x * 32;

    for (int idx = threadIdx.x; idx < 32 * 32; idx += 128) {
        int r = idx >> 5, q = idx & 31;
        int row = row0 + r;
        float4 v = make_float4(0.f, 0.f, 0.f, 0.f);
        if (row < N_NODES) v = ((const float4*)(g_h0 + (size_t)row * HID))[q];
        unsigned long long p0, p1, p2, p3;
        asm("mov.b64 %0, {%1, %1};" : "=l"(p0) : "r"(__float_as_uint(v.x)));
        asm("mov.b64 %0, {%1, %1};" : "=l"(p1) : "r"(__float_as_uint(v.y)));
        asm("mov.b64 %0, {%1, %1};" : "=l"(p2) : "r"(__float_as_uint(v.z)));
        asm("mov.b64 %0, {%1, %1};" : "=l"(p3) : "r"(__float_as_uint(v.w)));
        Ash[r][q * 4 + 0] = p0;
        Ash[r][q * 4 + 1] = p1;
        Ash[r][q * 4 + 2] = p2;
        Ash[r][q * 4 + 3] = p3;
    }
    __syncthreads();

    unsigned long long acc[8][2];
    #pragma unroll
    for (int r = 0; r < 8; r++) { acc[r][0] = 0ull; acc[r][1] = 0ull; }

    #pragma unroll 4
    for (int k = 0; k < HID; k++) {
        ulonglong2 w2 = ((const ulonglong2*)(W + (size_t)k * HID))[tx];
        #pragma unroll
        for (int r = 0; r < 8; r++) {
            unsigned long long a = Ash[ty * 8 + r][k];
            acc[r][0] = ffma2(a, w2.x, acc[r][0]);
            acc[r][1] = ffma2(a, w2.y, acc[r][1]);
        }
    }

    float4 bb = ((const float4*)b)[tx];
    #pragma unroll
    for (int r = 0; r < 8; r++) {
        int row = row0 + ty * 8 + r;
        if (row < N_NODES) {
            float2 lo = *(float2*)&acc[r][0];
            float2 hi = *(float2*)&acc[r][1];
            __half2 o0 = __floats2half2_rn(fmaxf(lo.x + bb.x, 0.f), fmaxf(lo.y + bb.y, 0.f));
            __half2 o1 = __floats2half2_rn(fmaxf(hi.x + bb.z, 0.f), fmaxf(hi.y + bb.w, 0.f));
            uint2 o;
            o.x = h2_as_u32(o0);
            o.y = h2_as_u32(o1);
            ((uint2*)(g_h1h + (size_t)row * HID))[tx] = o;
        }
    }
}

// ---------------- 128-dim aggregation: gathers fp16 g_h1h, writes fp32 g_h0
// g_h0[d] = dis[d]^2*h[d] + sum_e dis[s]*dis[d]*h[s]
__global__ void k_aggregate() {
    int node = blockIdx.x * (blockDim.x >> 5) + (threadIdx.x >> 5);
    if (node >= N_NODES) return;
    int lane = threadIdx.x & 31;
    float dd = g_dis[node];
    float s0 = dd * dd;
    uint2 pv = ((const uint2*)(g_h1h + (size_t)node * HID))[lane];
    float2 v0 = __half22float2(u32_as_h2(pv.x));
    float2 v1 = __half22float2(u32_as_h2(pv.y));
    float ax = v0.x * s0, ay = v0.y * s0, az = v1.x * s0, aw = v1.y * s0;
    int beg = real_off(node), end = real_off(node + 1);
    for (int e = beg; e < end; e++) {
        int s = g_srcs[e];
        float w = g_dis[s] * dd;
        uint2 ph = ((const uint2*)(g_h1h + (size_t)s * HID))[lane];
        float2 h0 = __half22float2(u32_as_h2(ph.x));
        float2 h1 = __half22float2(u32_as_h2(ph.y));
        ax += h0.x * w;
        ay += h0.y * w;
        az += h1.x * w;
        aw += h1.y * w;
    }
    ((float4*)(g_h0 + (size_t)node * HID))[lane] = make_float4(ax, ay, az, aw);
}

// ---------------- pooling + MLP ----------------
__global__ void k_pool() {
    int g = blockIdx.x, c = threadIdx.x;
    int s = g_gstart[g], e = g_gstart[g + 1];
    float acc = 0.f;
    for (int i = s; i < e; i++) acc += __half2float(g_h1h[(size_t)i * HID + c]);
    float cnt = (float)((e - s) > 1 ? (e - s) : 1);
    g_pooled[g * HID + c] = acc / cnt;
}

__global__ void k_fc1(const float* __restrict__ w, const float* __restrict__ b) {
    int g = blockIdx.x, j = threadIdx.x;  // 64 x 64
    float acc = b[j];
    #pragma unroll 8
    for (int k = 0; k < HID; k++) acc += g_pooled[g * HID + k] * w[k * 64 + j];
    g_z[g * 64 + j] = fmaxf(acc, 0.f);
}

__global__ void k_fc2(const float* __restrict__ w, const float* __restrict__ b,
                      float* __restrict__ out) {
    int g = threadIdx.x;  // 64
    float acc = b[0];
    #pragma unroll 8
    for (int j = 0; j < 64; j++) acc += g_z[g * 64 + j] * w[j];
    out[g] = acc;
}

// ---------------- launch ----------------
extern "C" void kernel_launch(void* const* d_in, const int* in_sizes, int n_in,
                              void* d_out, int out_size) {
    const float* x     = (const float*)d_in[0];
    const int*   ei    = (const int*)d_in[1];   // int64 narrowed to int32 by harness
    const int*   batch = (const int*)d_in[2];
    const float* W1 = (const float*)d_in[3];
    const float* b1 = (const float*)d_in[4];
    const float* W2 = (const float*)d_in[5];
    const float* b2 = (const float*)d_in[6];
    const float* W3 = (const float*)d_in[7];
    const float* b3 = (const float*)d_in[8];
    const float* fc1_w = (const float*)d_in[9];
    const float* fc1_b = (const float*)d_in[10];
    const float* fc2_w = (const float*)d_in[11];
    const float* fc2_b = (const float*)d_in[12];
    float* out = (float*)d_out;

    // graph structure (per-call: deterministic & self-contained)
    k_init<<<256, 256>>>();
    k_degree<<<(N_EDGES + 255) / 256, 256>>>(ei);
    k_scan1<<<SCAN_NB, 256>>>();
    k_scan2<<<1, 256>>>();
    k_fill<<<(N_EDGES + 255) / 256, 256>>>(ei);
    k_graph_bounds<<<(N_NODES + 255) / 256, 256>>>(batch);

    const int AGG_BLOCKS = (N_NODES + 7) / 8;   // 8 warps/block, 1 warp/node
    const int G128_BLOCKS = (N_NODES + 31) / 32;

    // layer 1: agg(x) @ W1 + b1, relu
    k_agg_x<<<(N_NODES + 255) / 256, 256>>>(x);
    k_gemm6<<<(N_NODES + 3) / 4, 256>>>(W1, b1);
    // layer 2: agg(h) @ W2 + b2, relu
    k_aggregate<<<AGG_BLOCKS, 256>>>();
    k_gemm128<<<G128_BLOCKS, 128>>>(W2, b2);
    // layer 3: agg(h) @ W3 + b3, relu
    k_aggregate<<<AGG_BLOCKS, 256>>>();
    k_gemm128<<<G128_BLOCKS, 128>>>(W3, b3);

    // pool + MLP
    k_pool<<<N_GRAPHS, HID>>>();
    k_fc1<<<N_GRAPHS, 64>>>(fc1_w, fc1_b);
    k_fc2<<<1, N_GRAPHS>>>(fc2_w, fc2_b, out);
}

// round 8
// speedup vs baseline: 1.3304x; 1.0689x over previous
#include <cuda_runtime.h>
#include <cuda_fp16.h>
#include <cuda_bf16.h>

#define N_NODES 50000
#define N_EDGES 600000
#define N_GRAPHS 64
#define HID 128
#define SCAN_NB ((N_NODES + 255) / 256)   // 196

__device__ __forceinline__ unsigned int h2_as_u32(__half2 h) {
    return *reinterpret_cast<unsigned int*>(&h);
}
__device__ __forceinline__ __half2 u32_as_h2(unsigned int u) {
    return *reinterpret_cast<__half2*>(&u);
}

// ---------------- scratch (static device globals; no allocation) ----------------
__device__ int    g_indeg[N_NODES];
__device__ float  g_dis[N_NODES];
__device__ int    g_offs[N_NODES + 1];    // chunk-local exclusive scans
__device__ int    g_fill[N_NODES];
__device__ int    g_srcs[N_EDGES];
__device__ int    g_bsum[256];            // per-chunk global offsets
__device__ float  g_h0[(size_t)N_NODES * HID];   // agg output (fp32, GEMM input)
__device__ __half g_h1h[(size_t)N_NODES * HID];  // GEMM output (fp16, gathered)
__device__ int    g_gstart[N_GRAPHS + 1];

__device__ __forceinline__ int real_off(int i) { return g_offs[i] + g_bsum[i >> 8]; }

// ---------------- graph preprocessing ----------------
__global__ void k_init() {
    for (int i = blockIdx.x * blockDim.x + threadIdx.x; i < N_NODES;
         i += gridDim.x * blockDim.x) {
        g_indeg[i] = 0;
        g_fill[i] = 0;
    }
}

__global__ void k_degree(const int* __restrict__ ei) {
    int i = blockIdx.x * blockDim.x + threadIdx.x;
    if (i >= N_EDGES) return;
    int d = ei[N_EDGES + i];
    if (d >= 0 && d < N_NODES) atomicAdd(&g_indeg[d], 1);
}

// ---- scan level 1 (chunk-local exclusive scan; writes g_dis; fused graph bounds)
__global__ void k_scan1(const int* __restrict__ batch) {
    __shared__ int wsum[8];
    int tid = threadIdx.x, lane = tid & 31, wid = tid >> 5;
    int i = blockIdx.x * 256 + tid;
    int v = (i < N_NODES) ? g_indeg[i] : 0;
    if (i < N_NODES) g_dis[i] = rsqrtf((float)(v + 1));  // +1 self-loop
    int s = v;
    #pragma unroll
    for (int o = 1; o < 32; o <<= 1) {
        int t = __shfl_up_sync(0xffffffffu, s, o);
        if (lane >= o) s += t;
    }
    if (lane == 31) wsum[wid] = s;
    __syncthreads();
    if (tid == 0) {
        int run = 0;
        #pragma unroll
        for (int j = 0; j < 8; j++) { int t = wsum[j]; wsum[j] = run; run += t; }
        g_bsum[blockIdx.x] = run;   // chunk total (scanned in level 2)
    }
    __syncthreads();
    int excl = wsum[wid] + (s - v);
    if (i <= N_NODES) g_offs[i] = excl;

    // fused: graph start boundaries from sorted batch
    if (i < N_NODES) {
        int b = batch[i];
        if (b < 0) b = 0;
        if (b >= N_GRAPHS) b = N_GRAPHS - 1;
        int prev;
        if (i == 0) prev = -1;
        else {
            prev = batch[i - 1];
            if (prev < 0) prev = 0;
            if (prev >= N_GRAPHS) prev = N_GRAPHS - 1;
        }
        for (int g = prev + 1; g <= b; g++) g_gstart[g] = i;
        if (i == N_NODES - 1)
            for (int g = b + 1; g <= N_GRAPHS; g++) g_gstart[g] = N_NODES;
    }
}

// ---- level 2: exclusive scan of chunk totals
__global__ void k_scan2() {
    __shared__ int wsum[8];
    int tid = threadIdx.x, lane = tid & 31, wid = tid >> 5;
    int v = (tid < SCAN_NB) ? g_bsum[tid] : 0;
    int s = v;
    #pragma unroll
    for (int o = 1; o < 32; o <<= 1) {
        int t = __shfl_up_sync(0xffffffffu, s, o);
        if (lane >= o) s += t;
    }
    if (lane == 31) wsum[wid] = s;
    __syncthreads();
    if (tid == 0) {
        int run = 0;
        #pragma unroll
        for (int j = 0; j < 8; j++) { int t = wsum[j]; wsum[j] = run; run += t; }
    }
    __syncthreads();
    int excl = wsum[wid] + (s - v);
    if (tid < SCAN_NB) g_bsum[tid] = excl;
}

__global__ void k_fill(const int* __restrict__ ei) {
    int i = blockIdx.x * blockDim.x + threadIdx.x;
    if (i >= N_EDGES) return;
    int s = ei[i];
    int d = ei[N_EDGES + i];
    if (s < 0 || s >= N_NODES || d < 0 || d >= N_NODES) return;
    int pos = real_off(d) + atomicAdd(&g_fill[d], 1);
    g_srcs[pos] = s;
}

// ---------------- fused layer 1: agg(x)[6] then @W1[6,128]+b1, relu -> g_h1h
// 256 threads/block = 256 nodes. Phase 1: per-thread 6-dim aggregate -> smem.
// Phase 2: 64 passes x 4 nodes, coalesced half2 writes.
__global__ void k_aggx_gemm6(const float* __restrict__ x,
                             const float* __restrict__ W,
                             const float* __restrict__ b) {
    __shared__ float Asm[256][6];
    int tid = threadIdx.x;
    int node = blockIdx.x * 256 + tid;

    if (node < N_NODES) {
        float dd = g_dis[node];
        float s0 = dd * dd;
        const float2* xr = (const float2*)(x + node * 6);
        float2 a0 = xr[0], a1 = xr[1], a2 = xr[2];
        a0.x *= s0; a0.y *= s0; a1.x *= s0; a1.y *= s0; a2.x *= s0; a2.y *= s0;
        int beg = real_off(node), end = real_off(node + 1);
        for (int e = beg; e < end; e++) {
            int s = g_srcs[e];
            float w = g_dis[s] * dd;
            const float2* xs = (const float2*)(x + s * 6);
            float2 v0 = xs[0], v1 = xs[1], v2 = xs[2];
            a0.x += v0.x * w; a0.y += v0.y * w;
            a1.x += v1.x * w; a1.y += v1.y * w;
            a2.x += v2.x * w; a2.y += v2.y * w;
        }
        Asm[tid][0] = a0.x; Asm[tid][1] = a0.y;
        Asm[tid][2] = a1.x; Asm[tid][3] = a1.y;
        Asm[tid][4] = a2.x; Asm[tid][5] = a2.y;
    }
    __syncthreads();

    // phase 2: tid -> (sub-node = tid>>6, colpair j = tid&63); 64 passes of 4 nodes
    int j = tid & 63;
    int c0 = j * 2;
    float w0[6], w1[6];
    #pragma unroll
    for (int k = 0; k < 6; k++) {
        w0[k] = __ldg(&W[k * HID + c0]);
        w1[k] = __ldg(&W[k * HID + c0 + 1]);
    }
    float bb0 = __ldg(&b[c0]), bb1 = __ldg(&b[c0 + 1]);
    int nbase = blockIdx.x * 256;
    for (int r = tid >> 6; r < 256; r += 4) {
        int row = nbase + r;
        if (row >= N_NODES) break;
        float acc0 = bb0, acc1 = bb1;
        #pragma unroll
        for (int k = 0; k < 6; k++) {
            float a = Asm[r][k];
            acc0 += a * w0[k];
            acc1 += a * w1[k];
        }
        __half2 h = __floats2half2_rn(fmaxf(acc0, 0.f), fmaxf(acc1, 0.f));
        ((__half2*)(g_h1h + (size_t)row * HID))[j] = h;
    }
}

// packed fp32x2 FMA (SASS FFMA2)
__device__ __forceinline__ unsigned long long ffma2(unsigned long long a,
                                                    unsigned long long b,
                                                    unsigned long long c) {
    unsigned long long d;
    asm("fma.rn.f32x2 %0, %1, %2, %3;" : "=l"(d) : "l"(a), "l"(b), "l"(c));
    return d;
}

// layers 2/3: g_h0[N,128] @ W[128,128] + b, relu -> g_h1h (fp16)
__global__ void k_gemm128(const float* __restrict__ W, const float* __restrict__ b) {
    __shared__ unsigned long long Ash[32][HID];   // 32 KB, duplicated {a,a}
    int ty = threadIdx.x >> 5;   // 0..3 : row group (8 rows)
    int tx = threadIdx.x & 31;   // 0..31 : col group (4 cols)
    int row0 = blockIdx.x * 32;

    for (int idx = threadIdx.x; idx < 32 * 32; idx += 128) {
        int r = idx >> 5, q = idx & 31;
        int row = row0 + r;
        float4 v = make_float4(0.f, 0.f, 0.f, 0.f);
        if (row < N_NODES) v = ((const float4*)(g_h0 + (size_t)row * HID))[q];
        unsigned long long p0, p1, p2, p3;
        asm("mov.b64 %0, {%1, %1};" : "=l"(p0) : "r"(__float_as_uint(v.x)));
        asm("mov.b64 %0, {%1, %1};" : "=l"(p1) : "r"(__float_as_uint(v.y)));
        asm("mov.b64 %0, {%1, %1};" : "=l"(p2) : "r"(__float_as_uint(v.z)));
        asm("mov.b64 %0, {%1, %1};" : "=l"(p3) : "r"(__float_as_uint(v.w)));
        Ash[r][q * 4 + 0] = p0;
        Ash[r][q * 4 + 1] = p1;
        Ash[r][q * 4 + 2] = p2;
        Ash[r][q * 4 + 3] = p3;
    }
    __syncthreads();

    unsigned long long acc[8][2];
    #pragma unroll
    for (int r = 0; r < 8; r++) { acc[r][0] = 0ull; acc[r][1] = 0ull; }

    #pragma unroll 4
    for (int k = 0; k < HID; k++) {
        ulonglong2 w2 = ((const ulonglong2*)(W + (size_t)k * HID))[tx];
        #pragma unroll
        for (int r = 0; r < 8; r++) {
            unsigned long long a = Ash[ty * 8 + r][k];
            acc[r][0] = ffma2(a, w2.x, acc[r][0]);
            acc[r][1] = ffma2(a, w2.y, acc[r][1]);
        }
    }

    float4 bb = ((const float4*)b)[tx];
    #pragma unroll
    for (int r = 0; r < 8; r++) {
        int row = row0 + ty * 8 + r;
        if (row < N_NODES) {
            float2 lo = *(float2*)&acc[r][0];
            float2 hi = *(float2*)&acc[r][1];
            __half2 o0 = __floats2half2_rn(fmaxf(lo.x + bb.x, 0.f), fmaxf(lo.y + bb.y, 0.f));
            __half2 o1 = __floats2half2_rn(fmaxf(hi.x + bb.z, 0.f), fmaxf(hi.y + bb.w, 0.f));
            uint2 o;
            o.x = h2_as_u32(o0);
            o.y = h2_as_u32(o1);
            ((uint2*)(g_h1h + (size_t)row * HID))[tx] = o;
        }
    }
}

// ---------------- 128-dim aggregation: gathers fp16 g_h1h, writes fp32 g_h0
__global__ void k_aggregate() {
    int node = blockIdx.x * (blockDim.x >> 5) + (threadIdx.x >> 5);
    if (node >= N_NODES) return;
    int lane = threadIdx.x & 31;
    float dd = g_dis[node];
    float s0 = dd * dd;
    uint2 pv = ((const uint2*)(g_h1h + (size_t)node * HID))[lane];
    float2 v0 = __half22float2(u32_as_h2(pv.x));
    float2 v1 = __half22float2(u32_as_h2(pv.y));
    float ax = v0.x * s0, ay = v0.y * s0, az = v1.x * s0, aw = v1.y * s0;
    int beg = real_off(node), end = real_off(node + 1);
    for (int e = beg; e < end; e++) {
        int s = g_srcs[e];
        float w = g_dis[s] * dd;
        uint2 ph = ((const uint2*)(g_h1h + (size_t)s * HID))[lane];
        float2 h0 = __half22float2(u32_as_h2(ph.x));
        float2 h1 = __half22float2(u32_as_h2(ph.y));
        ax += h0.x * w;
        ay += h0.y * w;
        az += h1.x * w;
        aw += h1.y * w;
    }
    ((float4*)(g_h0 + (size_t)node * HID))[lane] = make_float4(ax, ay, az, aw);
}

// ---------------- fused pool + fc1 + fc2: one block per graph ----------------
__global__ void k_pool_fc(const float* __restrict__ fc1_w, const float* __restrict__ fc1_b,
                          const float* __restrict__ fc2_w, const float* __restrict__ fc2_b,
                          float* __restrict__ out) {
    __shared__ float pooled[HID];
    __shared__ float z[64];
    int g = blockIdx.x, c = threadIdx.x;   // 128 threads
    int s = g_gstart[g], e = g_gstart[g + 1];
    float acc = 0.f;
    for (int i = s; i < e; i++) acc += __half2float(g_h1h[(size_t)i * HID + c]);
    float cnt = (float)((e - s) > 1 ? (e - s) : 1);
    pooled[c] = acc / cnt;
    __syncthreads();
    if (c < 64) {
        float a = fc1_b[c];
        #pragma unroll 8
        for (int k = 0; k < HID; k++) a += pooled[k] * fc1_w[k * 64 + c];
        z[c] = fmaxf(a, 0.f);
    }
    __syncthreads();
    if (c == 0) {
        float a = fc2_b[0];
        #pragma unroll 8
        for (int j = 0; j < 64; j++) a += z[j] * fc2_w[j];
        out[g] = a;
    }
}

// ---------------- launch ----------------
extern "C" void kernel_launch(void* const* d_in, const int* in_sizes, int n_in,
                              void* d_out, int out_size) {
    const float* x     = (const float*)d_in[0];
    const int*   ei    = (const int*)d_in[1];   // int64 narrowed to int32 by harness
    const int*   batch = (const int*)d_in[2];
    const float* W1 = (const float*)d_in[3];
    const float* b1 = (const float*)d_in[4];
    const float* W2 = (const float*)d_in[5];
    const float* b2 = (const float*)d_in[6];
    const float* W3 = (const float*)d_in[7];
    const float* b3 = (const float*)d_in[8];
    const float* fc1_w = (const float*)d_in[9];
    const float* fc1_b = (const float*)d_in[10];
    const float* fc2_w = (const float*)d_in[11];
    const float* fc2_b = (const float*)d_in[12];
    float* out = (float*)d_out;

    k_init<<<256, 256>>>();
    k_degree<<<(N_EDGES + 255) / 256, 256>>>(ei);
    k_scan1<<<SCAN_NB, 256>>>(batch);
    k_scan2<<<1, 256>>>();
    k_fill<<<(N_EDGES + 255) / 256, 256>>>(ei);

    const int AGG_BLOCKS = (N_NODES + 7) / 8;   // 8 warps/block, 1 warp/node
    const int G128_BLOCKS = (N_NODES + 31) / 32;

    // layer 1 (fused agg + 6x128 gemm)
    k_aggx_gemm6<<<(N_NODES + 255) / 256, 256>>>(x, W1, b1);
    // layer 2
    k_aggregate<<<AGG_BLOCKS, 256>>>();
    k_gemm128<<<G128_BLOCKS, 128>>>(W2, b2);
    // layer 3
    k_aggregate<<<AGG_BLOCKS, 256>>>();
    k_gemm128<<<G128_BLOCKS, 128>>>(W3, b3);

    // fused pool + MLP
    k_pool_fc<<<N_GRAPHS, HID>>>(fc1_w, fc1_b, fc2_w, fc2_b, out);
}

// round 12
// speedup vs baseline: 1.4117x; 1.0611x over previous
#include <cuda_runtime.h>
#include <cuda_fp16.h>
#include <cuda_bf16.h>
#include <cstdint>

#define N_NODES 50000
#define N_EDGES 600000
#define N_GRAPHS 64
#define HID 128
#define SCAN_NB ((N_NODES + 255) / 256)   // 196

__device__ __forceinline__ unsigned int h2_as_u32(__half2 h) {
    return *reinterpret_cast<unsigned int*>(&h);
}
__device__ __forceinline__ __half2 u32_as_h2(unsigned int u) {
    return *reinterpret_cast<__half2*>(&u);
}
__device__ __forceinline__ uint32_t smem_u32(const void* p) {
    uint32_t a;
    asm("{ .reg .u64 t; cvta.to.shared.u64 t, %1; cvt.u32.u64 %0, t; }" : "=r"(a) : "l"(p));
    return a;
}

// ---------------- scratch (static device globals; no allocation) ----------------
__device__ int    g_indeg[N_NODES];
__device__ float  g_dis[N_NODES];
__device__ int    g_offs[N_NODES + 1];
__device__ int    g_fill[N_NODES];
__device__ int    g_srcs[N_EDGES];
__device__ int    g_bsum[256];
__device__ float  g_h0[(size_t)N_NODES * HID];   // agg output (fp32, GEMM A operand)
__device__ __half g_h1h[(size_t)N_NODES * HID];  // GEMM output (fp16, gathered)
__device__ int    g_gstart[N_GRAPHS + 1];

__device__ __forceinline__ int real_off(int i) { return g_offs[i] + g_bsum[i >> 8]; }

// ---------------- graph preprocessing ----------------
__global__ void k_init() {
    for (int i = blockIdx.x * blockDim.x + threadIdx.x; i < N_NODES;
         i += gridDim.x * blockDim.x) {
        g_indeg[i] = 0;
        g_fill[i] = 0;
    }
}

__global__ void k_degree(const int* __restrict__ ei) {
    int i = blockIdx.x * blockDim.x + threadIdx.x;
    if (i >= N_EDGES) return;
    int d = ei[N_EDGES + i];
    if (d >= 0 && d < N_NODES) atomicAdd(&g_indeg[d], 1);
}

__global__ void k_scan1(const int* __restrict__ batch) {
    __shared__ int wsum[8];
    int tid = threadIdx.x, lane = tid & 31, wid = tid >> 5;
    int i = blockIdx.x * 256 + tid;
    int v = (i < N_NODES) ? g_indeg[i] : 0;
    if (i < N_NODES) g_dis[i] = rsqrtf((float)(v + 1));
    int s = v;
    #pragma unroll
    for (int o = 1; o < 32; o <<= 1) {
        int t = __shfl_up_sync(0xffffffffu, s, o);
        if (lane >= o) s += t;
    }
    if (lane == 31) wsum[wid] = s;
    __syncthreads();
    if (tid == 0) {
        int run = 0;
        #pragma unroll
        for (int j = 0; j < 8; j++) { int t = wsum[j]; wsum[j] = run; run += t; }
        g_bsum[blockIdx.x] = run;
    }
    __syncthreads();
    int excl = wsum[wid] + (s - v);
    if (i <= N_NODES) g_offs[i] = excl;

    if (i < N_NODES) {
        int b = batch[i];
        if (b < 0) b = 0;
        if (b >= N_GRAPHS) b = N_GRAPHS - 1;
        int prev;
        if (i == 0) prev = -1;
        else {
            prev = batch[i - 1];
            if (prev < 0) prev = 0;
            if (prev >= N_GRAPHS) prev = N_GRAPHS - 1;
        }
        for (int g = prev + 1; g <= b; g++) g_gstart[g] = i;
        if (i == N_NODES - 1)
            for (int g = b + 1; g <= N_GRAPHS; g++) g_gstart[g] = N_NODES;
    }
}

__global__ void k_scan2() {
    __shared__ int wsum[8];
    int tid = threadIdx.x, lane = tid & 31, wid = tid >> 5;
    int v = (tid < SCAN_NB) ? g_bsum[tid] : 0;
    int s = v;
    #pragma unroll
    for (int o = 1; o < 32; o <<= 1) {
        int t = __shfl_up_sync(0xffffffffu, s, o);
        if (lane >= o) s += t;
    }
    if (lane == 31) wsum[wid] = s;
    __syncthreads();
    if (tid == 0) {
        int run = 0;
        #pragma unroll
        for (int j = 0; j < 8; j++) { int t = wsum[j]; wsum[j] = run; run += t; }
    }
    __syncthreads();
    int excl = wsum[wid] + (s - v);
    if (tid < SCAN_NB) g_bsum[tid] = excl;
}

__global__ void k_fill(const int* __restrict__ ei) {
    int i = blockIdx.x * blockDim.x + threadIdx.x;
    if (i >= N_EDGES) return;
    int s = ei[i];
    int d = ei[N_EDGES + i];
    if (s < 0 || s >= N_NODES || d < 0 || d >= N_NODES) return;
    int pos = real_off(d) + atomicAdd(&g_fill[d], 1);
    g_srcs[pos] = s;
}

// ---------------- fused layer 1: agg(x)[6] then @W1[6,128]+b1, relu -> g_h1h
__global__ void k_aggx_gemm6(const float* __restrict__ x,
                             const float* __restrict__ W,
                             const float* __restrict__ b) {
    __shared__ float Asm[256][6];
    int tid = threadIdx.x;
    int node = blockIdx.x * 256 + tid;

    if (node < N_NODES) {
        float dd = g_dis[node];
        float s0 = dd * dd;
        const float2* xr = (const float2*)(x + node * 6);
        float2 a0 = xr[0], a1 = xr[1], a2 = xr[2];
        a0.x *= s0; a0.y *= s0; a1.x *= s0; a1.y *= s0; a2.x *= s0; a2.y *= s0;
        int beg = real_off(node), end = real_off(node + 1);
        for (int e = beg; e < end; e++) {
            int s = g_srcs[e];
            float w = g_dis[s] * dd;
            const float2* xs = (const float2*)(x + s * 6);
            float2 v0 = xs[0], v1 = xs[1], v2 = xs[2];
            a0.x += v0.x * w; a0.y += v0.y * w;
            a1.x += v1.x * w; a1.y += v1.y * w;
            a2.x += v2.x * w; a2.y += v2.y * w;
        }
        Asm[tid][0] = a0.x; Asm[tid][1] = a0.y;
        Asm[tid][2] = a1.x; Asm[tid][3] = a1.y;
        Asm[tid][4] = a2.x; Asm[tid][5] = a2.y;
    }
    __syncthreads();

    int j = tid & 63;
    int c0 = j * 2;
    float w0[6], w1[6];
    #pragma unroll
    for (int k = 0; k < 6; k++) {
        w0[k] = __ldg(&W[k * HID + c0]);
        w1[k] = __ldg(&W[k * HID + c0 + 1]);
    }
    float bb0 = __ldg(&b[c0]), bb1 = __ldg(&b[c0 + 1]);
    int nbase = blockIdx.x * 256;
    for (int r = tid >> 6; r < 256; r += 4) {
        int row = nbase + r;
        if (row >= N_NODES) break;
        float acc0 = bb0, acc1 = bb1;
        #pragma unroll
        for (int k = 0; k < 6; k++) {
            float a = Asm[r][k];
            acc0 += a * w0[k];
            acc1 += a * w1[k];
        }
        __half2 h = __floats2half2_rn(fmaxf(acc0, 0.f), fmaxf(acc1, 0.f));
        ((__half2*)(g_h1h + (size_t)row * HID))[j] = h;
    }
}

// ---------------- split-fp16 HMMA GEMM: g_h0[N,128](f32) @ W[128,128] + b, relu -> g_h1h
// A = A_hi + A_lo, W = W_hi + W_lo (fp16 pairs); D += Ahi*Whi + Ahi*Wlo + Alo*Whi
// in fp32 accumulators -> effectively fp32-precision operands.
#define SA 136                                       // padded row stride (halfs)
#define SMEM_MMA_BYTES (4 * 128 * SA * 2 + 512)      // Ahi,Alo,Bhi,Blo + bias
__global__ void k_gemm128_mma(const float* __restrict__ W, const float* __restrict__ b) {
    extern __shared__ __half sm[];
    __half* Ahi = sm;
    __half* Alo = sm + 128 * SA;
    __half* Bhi = sm + 2 * 128 * SA;     // Bhi[n][k] = fp16(W[k][n])
    __half* Blo = sm + 3 * 128 * SA;
    float*  bs  = (float*)(sm + 4 * 128 * SA);
    int tid = threadIdx.x;
    int wid = tid >> 5, lane = tid & 31;
    int row0 = blockIdx.x * 128;

    // stage A tile (fp32 rows from g_h0 -> hi/lo fp16), zero-pad OOB rows
    for (int idx = tid; idx < 128 * 32; idx += 256) {
        int r = idx >> 5, q = idx & 31;
        float4 v = make_float4(0.f, 0.f, 0.f, 0.f);
        int row = row0 + r;
        if (row < N_NODES) v = ((const float4*)(g_h0 + (size_t)row * HID))[q];
        __half hx = __float2half_rn(v.x), hy = __float2half_rn(v.y);
        __half hz = __float2half_rn(v.z), hw = __float2half_rn(v.w);
        __half lx = __float2half_rn(v.x - __half2float(hx));
        __half ly = __float2half_rn(v.y - __half2float(hy));
        __half lz = __float2half_rn(v.z - __half2float(hz));
        __half lw = __float2half_rn(v.w - __half2float(hw));
        uint2 ph, pl;
        ph.x = h2_as_u32(__halves2half2(hx, hy));
        ph.y = h2_as_u32(__halves2half2(hz, hw));
        pl.x = h2_as_u32(__halves2half2(lx, ly));
        pl.y = h2_as_u32(__halves2half2(lz, lw));
        *(uint2*)(Ahi + r * SA + q * 4) = ph;
        *(uint2*)(Alo + r * SA + q * 4) = pl;
    }
    // stage B = W^T hi/lo (coalesced W read)
    for (int idx = tid; idx < 128 * 128; idx += 256) {
        int k = idx >> 7, n = idx & 127;
        float w = __ldg(&W[idx]);
        __half hi = __float2half_rn(w);
        __half lo = __float2half_rn(w - __half2float(hi));
        Bhi[n * SA + k] = hi;
        Blo[n * SA + k] = lo;
    }
    if (tid < 128) bs[tid] = __ldg(&b[tid]);
    __syncthreads();

    uint32_t ahi_base = smem_u32(Ahi), alo_base = smem_u32(Alo);
    uint32_t bhi_base = smem_u32(Bhi), blo_base = smem_u32(Blo);
    int R0 = wid * 16;

    float d[16][4];
    #pragma unroll
    for (int nt = 0; nt < 16; nt++)
        #pragma unroll
        for (int q = 0; q < 4; q++) d[nt][q] = 0.f;

    #pragma unroll
    for (int kt = 0; kt < 8; kt++) {
        int k0 = kt * 16;
        uint32_t aoff =
            ((uint32_t)((R0 + (lane & 15)) * SA + k0 + ((lane >> 4) << 3)) << 1);
        uint32_t ah0, ah1, ah2, ah3, al0, al1, al2, al3;
        asm volatile("ldmatrix.sync.aligned.m8n8.x4.shared.b16 {%0,%1,%2,%3}, [%4];"
                     : "=r"(ah0), "=r"(ah1), "=r"(ah2), "=r"(ah3) : "r"(ahi_base + aoff));
        asm volatile("ldmatrix.sync.aligned.m8n8.x4.shared.b16 {%0,%1,%2,%3}, [%4];"
                     : "=r"(al0), "=r"(al1), "=r"(al2), "=r"(al3) : "r"(alo_base + aoff));
        #pragma unroll
        for (int nt = 0; nt < 16; nt++) {
            int n0 = nt * 8;
            uint32_t boff =
                ((uint32_t)((n0 + (lane & 7)) * SA + k0 + (lane & 8)) << 1);
            uint32_t bh0, bh1, bl0, bl1;
            asm volatile("ldmatrix.sync.aligned.m8n8.x2.shared.b16 {%0,%1}, [%2];"
                         : "=r"(bh0), "=r"(bh1) : "r"(bhi_base + boff));
            asm volatile("ldmatrix.sync.aligned.m8n8.x2.shared.b16 {%0,%1}, [%2];"
                         : "=r"(bl0), "=r"(bl1) : "r"(blo_base + boff));
            asm volatile(
                "mma.sync.aligned.m16n8k16.row.col.f32.f16.f16.f32 "
                "{%0,%1,%2,%3}, {%4,%5,%6,%7}, {%8,%9}, {%0,%1,%2,%3};"
                : "+f"(d[nt][0]), "+f"(d[nt][1]), "+f"(d[nt][2]), "+f"(d[nt][3])
                : "r"(ah0), "r"(ah1), "r"(ah2), "r"(ah3), "r"(bh0), "r"(bh1));
            asm volatile(
                "mma.sync.aligned.m16n8k16.row.col.f32.f16.f16.f32 "
                "{%0,%1,%2,%3}, {%4,%5,%6,%7}, {%8,%9}, {%0,%1,%2,%3};"
                : "+f"(d[nt][0]), "+f"(d[nt][1]), "+f"(d[nt][2]), "+f"(d[nt][3])
                : "r"(ah0), "r"(ah1), "r"(ah2), "r"(ah3), "r"(bl0), "r"(bl1));
            asm volatile(
                "mma.sync.aligned.m16n8k16.row.col.f32.f16.f16.f32 "
                "{%0,%1,%2,%3}, {%4,%5,%6,%7}, {%8,%9}, {%0,%1,%2,%3};"
                : "+f"(d[nt][0]), "+f"(d[nt][1]), "+f"(d[nt][2]), "+f"(d[nt][3])
                : "r"(al0), "r"(al1), "r"(al2), "r"(al3), "r"(bh0), "r"(bh1));
        }
    }

    // epilogue: bias + relu + fp16 pack; d0,d1 -> row (lane>>2), d2,d3 -> +8
    int rA = row0 + R0 + (lane >> 2);
    int rB = rA + 8;
    int cl = (lane & 3) * 2;
    #pragma unroll
    for (int nt = 0; nt < 16; nt++) {
        int n0 = nt * 8 + cl;
        float bb0 = bs[n0], bb1 = bs[n0 + 1];
        if (rA < N_NODES) {
            __half2 h = __floats2half2_rn(fmaxf(d[nt][0] + bb0, 0.f),
                                          fmaxf(d[nt][1] + bb1, 0.f));
            *(__half2*)(g_h1h + (size_t)rA * HID + n0) = h;
        }
        if (rB < N_NODES) {
            __half2 h = __floats2half2_rn(fmaxf(d[nt][2] + bb0, 0.f),
                                          fmaxf(d[nt][3] + bb1, 0.f));
            *(__half2*)(g_h1h + (size_t)rB * HID + n0) = h;
        }
    }
}

// ---------------- 128-dim aggregation: gathers fp16 g_h1h, writes fp32 g_h0
__global__ void k_aggregate() {
    int node = blockIdx.x * (blockDim.x >> 5) + (threadIdx.x >> 5);
    if (node >= N_NODES) return;
    int lane = threadIdx.x & 31;
    float dd = g_dis[node];
    float s0 = dd * dd;
    uint2 pv = ((const uint2*)(g_h1h + (size_t)node * HID))[lane];
    float2 v0 = __half22float2(u32_as_h2(pv.x));
    float2 v1 = __half22float2(u32_as_h2(pv.y));
    float ax = v0.x * s0, ay = v0.y * s0, az = v1.x * s0, aw = v1.y * s0;
    int beg = real_off(node), end = real_off(node + 1);
    for (int e = beg; e < end; e++) {
        int s = g_srcs[e];
        float w = g_dis[s] * dd;
        uint2 ph = ((const uint2*)(g_h1h + (size_t)s * HID))[lane];
        float2 h0 = __half22float2(u32_as_h2(ph.x));
        float2 h1 = __half22float2(u32_as_h2(ph.y));
        ax += h0.x * w;
        ay += h0.y * w;
        az += h1.x * w;
        aw += h1.y * w;
    }
    ((float4*)(g_h0 + (size_t)node * HID))[lane] = make_float4(ax, ay, az, aw);
}

// ---------------- fused pool + fc1 + fc2 ----------------
__global__ void k_pool_fc(const float* __restrict__ fc1_w, const float* __restrict__ fc1_b,
                          const float* __restrict__ fc2_w, const float* __restrict__ fc2_b,
                          float* __restrict__ out) {
    __shared__ float pooled[HID];
    __shared__ float z[64];
    int g = blockIdx.x, c = threadIdx.x;
    int s = g_gstart[g], e = g_gstart[g + 1];
    float acc = 0.f;
    for (int i = s; i < e; i++) acc += __half2float(g_h1h[(size_t)i * HID + c]);
    float cnt = (float)((e - s) > 1 ? (e - s) : 1);
    pooled[c] = acc / cnt;
    __syncthreads();
    if (c < 64) {
        float a = fc1_b[c];
        #pragma unroll 8
        for (int k = 0; k < HID; k++) a += pooled[k] * fc1_w[k * 64 + c];
        z[c] = fmaxf(a, 0.f);
    }
    __syncthreads();
    if (c == 0) {
        float a = fc2_b[0];
        #pragma unroll 8
        for (int j = 0; j < 64; j++) a += z[j] * fc2_w[j];
        out[g] = a;
    }
}

// ---------------- launch ----------------
extern "C" void kernel_launch(void* const* d_in, const int* in_sizes, int n_in,
                              void* d_out, int out_size) {
    const float* x     = (const float*)d_in[0];
    const int*   ei    = (const int*)d_in[1];   // int64 narrowed to int32 by harness
    const int*   batch = (const int*)d_in[2];
    const float* W1 = (const float*)d_in[3];
    const float* b1 = (const float*)d_in[4];
    const float* W2 = (const float*)d_in[5];
    const float* b2 = (const float*)d_in[6];
    const float* W3 = (const float*)d_in[7];
    const float* b3 = (const float*)d_in[8];
    const float* fc1_w = (const float*)d_in[9];
    const float* fc1_b = (const float*)d_in[10];
    const float* fc2_w = (const float*)d_in[11];
    const float* fc2_b = (const float*)d_in[12];
    float* out = (float*)d_out;

    cudaFuncSetAttribute(k_gemm128_mma,
                         cudaFuncAttributeMaxDynamicSharedMemorySize, SMEM_MMA_BYTES);

    k_init<<<256, 256>>>();
    k_degree<<<(N_EDGES + 255) / 256, 256>>>(ei);
    k_scan1<<<SCAN_NB, 256>>>(batch);
    k_scan2<<<1, 256>>>();
    k_fill<<<(N_EDGES + 255) / 256, 256>>>(ei);

    const int AGG_BLOCKS = (N_NODES + 7) / 8;
    const int TC_BLOCKS = (N_NODES + 127) / 128;   // 391

    // layer 1 (fused agg + 6x128 gemm)
    k_aggx_gemm6<<<(N_NODES + 255) / 256, 256>>>(x, W1, b1);
    // layer 2
    k_aggregate<<<AGG_BLOCKS, 256>>>();
    k_gemm128_mma<<<TC_BLOCKS, 256, SMEM_MMA_BYTES>>>(W2, b2);
    // layer 3
    k_aggregate<<<AGG_BLOCKS, 256>>>();
    k_gemm128_mma<<<TC_BLOCKS, 256, SMEM_MMA_BYTES>>>(W3, b3);

    // fused pool + MLP
    k_pool_fc<<<N_GRAPHS, HID>>>(fc1_w, fc1_b, fc2_w, fc2_b, out);
}